// round 15
// baseline (speedup 1.0000x reference)
#include <cuda_runtime.h>
#include <cuda_bf16.h>
#include <cstdint>

// CrossAttention_86165633892747 — collapses algebraically:
//   softmax over a size-1 axis == 1  =>  attn == v
//   out = chem @ (Wout @ Wv)^T + (Wout @ bv + bout)
// Single 16x16 affine map of chem_16. fp_16 / Wq / Wk are dead.
//
// R13: L1 was 74.9% (LDG/STG with 64B lane stride = 16 wf/instr). New layout:
// 4 lanes per row, each owning one float4 quarter -> fully coalesced 512B
// warp accesses (4 wf/instr). Matrix column-block lives in registers; 4-lane
// partial sums combined with a static-index rotated shuffle reduction.

#define DIMC 16

// g_Mq[q][i][s] = float4( M[4*qq+0][4q+i], M[4*qq+1][4q+i],
//                         M[4*qq+2][4q+i], M[4*qq+3][4q+i] ),  qq=(q+s)&3
// (lane-q's matrix block, outputs grouped in rotated quarter order)
__device__ float4 g_Mq[4][4][4];
__device__ float4 g_c4[4];   // c quarters

__global__ void ca_setup_kernel(const float* __restrict__ in_w,   // [48,16]
                                const float* __restrict__ in_b,   // [48]
                                const float* __restrict__ out_w,  // [16,16]
                                const float* __restrict__ out_b)  // [16]
{
    __shared__ float sM[DIMC][DIMC];
    __shared__ float sC[DIMC];
    const int t = threadIdx.x;              // 0..255
    const int o = t >> 4;                   // output row
    const int i = t & 15;                   // input col
    const float* Wv = in_w + 2 * DIMC * DIMC;   // rows 32..47
    const float* bv = in_b + 2 * DIMC;

    // M[o][i] = sum_k Wout[o][k] * Wv[k][i]
    float s = 0.f;
#pragma unroll
    for (int k = 0; k < DIMC; ++k)
        s = fmaf(out_w[o * DIMC + k], Wv[k * DIMC + i], s);
    sM[o][i] = s;

    if (t < DIMC) {                          // c[t] = bout[t] + Wout[t]·bv
        float c = out_b[t];
#pragma unroll
        for (int k = 0; k < DIMC; ++k)
            c = fmaf(out_w[t * DIMC + k], bv[k], c);
        sC[t] = c;
    }
    __syncthreads();

    if (t < 64) {                            // t = q*16 + i*4 + s
        int q = t >> 4, ii = (t >> 2) & 3, ss = t & 3;
        int qq = (q + ss) & 3;
        int col = 4 * q + ii;
        g_Mq[q][ii][ss] = make_float4(sM[4 * qq + 0][col], sM[4 * qq + 1][col],
                                      sM[4 * qq + 2][col], sM[4 * qq + 3][col]);
    }
    if (t < 4)
        g_c4[t] = make_float4(sC[4 * t], sC[4 * t + 1], sC[4 * t + 2], sC[4 * t + 3]);
}

// ---- packed f32x2 helpers (f32x2 ops are PTX-only; ptxas won't auto-fuse) ----
__device__ __forceinline__ unsigned long long bcast2(float x) {
    unsigned long long r;
    asm("mov.b64 %0, {%1, %1};" : "=l"(r) : "f"(x));
    return r;
}
__device__ __forceinline__ unsigned long long ffma2(unsigned long long a,
                                                    unsigned long long b,
                                                    unsigned long long c) {
    unsigned long long d;
    asm("fma.rn.f32x2 %0, %1, %2, %3;" : "=l"(d) : "l"(a), "l"(b), "l"(c));
    return d;
}
__device__ __forceinline__ unsigned long long add2(unsigned long long a,
                                                   unsigned long long b) {
    unsigned long long d;
    asm("add.rn.f32x2 %0, %1, %2;" : "=l"(d) : "l"(a), "l"(b));
    return d;
}
__device__ __forceinline__ float2 unpack2(unsigned long long v) {
    float2 r;
    asm("mov.b64 {%0, %1}, %2;" : "=f"(r.x), "=f"(r.y) : "l"(v));
    return r;
}
__device__ __forceinline__ unsigned long long pack2(float lo, float hi) {
    unsigned long long r;
    asm("mov.b64 %0, {%1, %2};" : "=l"(r) : "f"(lo), "f"(hi));
    return r;
}
__device__ __forceinline__ unsigned long long shfl64(unsigned long long v, int src) {
    return __shfl_sync(0xffffffffu, v, src, 32);
}

#define ITERS 8   // row-groups per thread; block covers 64 rows per iter

__global__ void __launch_bounds__(256, 2)
ca_apply_kernel(const float* __restrict__ x,  // chem_16 [B,16]
                float* __restrict__ out,      // [B,16]
                unsigned int nrows)
{
    __shared__ float4 sMq[4][4][4];          // 1 KB
    __shared__ float4 sc4[4];

    const int t = threadIdx.x;
    if (t < 64) {
        int q = t >> 4, ii = (t >> 2) & 3, ss = t & 3;
        sMq[q][ii][ss] = g_Mq[q][ii][ss];
    } else if (t < 68) {
        sc4[t - 64] = g_c4[t - 64];
    }
    __syncthreads();

    const int lane = t & 31;
    const int q    = lane & 3;               // quarter owned by this lane
    const int grp  = lane & 28;
    const int src1 = grp | ((q + 1) & 3);
    const int src2 = grp | ((q + 2) & 3);
    const int src3 = grp | ((q + 3) & 3);

    // Matrix block into registers: mm[i*4+s] = two f32x2 pairs of quarter (q+s)&3
    ulonglong2 mm[16];
#pragma unroll
    for (int i = 0; i < 4; ++i)
#pragma unroll
        for (int s = 0; s < 4; ++s)
            mm[i * 4 + s] = *reinterpret_cast<const ulonglong2*>(&sMq[q][i][s]);

    unsigned long long cb0, cb1;
    { float4 c = sc4[q]; cb0 = pack2(c.x, c.y); cb1 = pack2(c.z, c.w); }

    const unsigned int row0 = blockIdx.x * (64u * ITERS) + (unsigned int)(t >> 2);
    const float4* xp = reinterpret_cast<const float4*>(x);
    float4*       op = reinterpret_cast<float4*>(out);
    const size_t  idx0 = (size_t)row0 * 4 + q;   // lane-contiguous float4 index

    // 4-deep prefetch ring for memory-level parallelism
    float4 buf[4];
#pragma unroll
    for (int k = 0; k < 4; ++k) {
        unsigned int r = row0 + 64u * k;
        buf[k] = (r < nrows) ? __ldcs(xp + idx0 + 256u * k)
                             : make_float4(0.f, 0.f, 0.f, 0.f);
    }

#pragma unroll
    for (int it = 0; it < ITERS; ++it) {
        float4 xv = buf[it & 3];
        if (it + 4 < ITERS) {
            unsigned int r = row0 + 64u * (it + 4);
            buf[it & 3] = (r < nrows) ? __ldcs(xp + idx0 + 256u * (it + 4))
                                      : make_float4(0.f, 0.f, 0.f, 0.f);
        }

        // partials: a[s*2+j] covers outputs of quarter (q+s)&3; bias seeds slot 0
        unsigned long long a[8];
        a[0] = cb0; a[1] = cb1;
        a[2] = 0ull; a[3] = 0ull; a[4] = 0ull; a[5] = 0ull; a[6] = 0ull; a[7] = 0ull;

        const float xi[4] = { xv.x, xv.y, xv.z, xv.w };
#pragma unroll
        for (int i = 0; i < 4; ++i) {
            const unsigned long long xx = bcast2(xi[i]);
#pragma unroll
            for (int s = 0; s < 4; ++s) {
                a[s * 2 + 0] = ffma2(xx, mm[i * 4 + s].x, a[s * 2 + 0]);
                a[s * 2 + 1] = ffma2(xx, mm[i * 4 + s].y, a[s * 2 + 1]);
            }
        }

        // rotated shuffle reduction: lane q gathers quarter q from all 4 lanes
        unsigned long long f0 = a[0], f1 = a[1];
        f0 = add2(f0, shfl64(a[6], src1));   // sender slot 3
        f1 = add2(f1, shfl64(a[7], src1));
        f0 = add2(f0, shfl64(a[4], src2));   // sender slot 2
        f1 = add2(f1, shfl64(a[5], src2));
        f0 = add2(f0, shfl64(a[2], src3));   // sender slot 1
        f1 = add2(f1, shfl64(a[3], src3));

        const unsigned int r = row0 + 64u * it;
        if (r < nrows) {
            float2 u = unpack2(f0), v = unpack2(f1);
            __stcs(op + idx0 + 256u * it, make_float4(u.x, u.y, v.x, v.y));
        }
    }
}

extern "C" void kernel_launch(void* const* d_in, const int* in_sizes, int n_in,
                              void* d_out, int out_size)
{
    // inputs: 0=fp_16 (unused), 1=chem_16, 2=in_proj_weight, 3=in_proj_bias,
    //         4=out_proj_weight, 5=out_proj_bias
    const float* chem  = (const float*)d_in[1];
    const float* in_w  = (const float*)d_in[2];
    const float* in_b  = (const float*)d_in[3];
    const float* out_w = (const float*)d_in[4];
    const float* out_b = (const float*)d_in[5];
    float* out = (float*)d_out;

    const unsigned int nrows = (unsigned int)(in_sizes[1] / DIMC);

    ca_setup_kernel<<<1, 256>>>(in_w, in_b, out_w, out_b);

    const unsigned int rows_per_block = 64u * ITERS;
    const unsigned int blocks = (nrows + rows_per_block - 1u) / rows_per_block;
    ca_apply_kernel<<<blocks, 256>>>(chem, out, nrows);
}

// round 16
// speedup vs baseline: 1.0115x; 1.0115x over previous
#include <cuda_runtime.h>
#include <cuda_bf16.h>
#include <cstdint>

// CrossAttention_86165633892747 — collapses algebraically:
//   softmax over a size-1 axis == 1  =>  attn == v
//   out = chem @ (Wout @ Wv)^T + (Wout @ bv + bout)
// Single 16x16 affine map of chem_16. fp_16 / Wq / Wk are dead.
//
// R13: L1 was 74.9% (LDG/STG with 64B lane stride = 16 wf/instr). New layout:
// 4 lanes per row, each owning one float4 quarter -> fully coalesced 512B
// warp accesses (4 wf/instr). Matrix column-block lives in registers; 4-lane
// partial sums combined with a static-index rotated shuffle reduction.

#define DIMC 16

// g_Mq[q][i][s] = float4( M[4*qq+0][4q+i], M[4*qq+1][4q+i],
//                         M[4*qq+2][4q+i], M[4*qq+3][4q+i] ),  qq=(q+s)&3
// (lane-q's matrix block, outputs grouped in rotated quarter order)
__device__ float4 g_Mq[4][4][4];
__device__ float4 g_c4[4];   // c quarters

__global__ void ca_setup_kernel(const float* __restrict__ in_w,   // [48,16]
                                const float* __restrict__ in_b,   // [48]
                                const float* __restrict__ out_w,  // [16,16]
                                const float* __restrict__ out_b)  // [16]
{
    __shared__ float sM[DIMC][DIMC];
    __shared__ float sC[DIMC];
    const int t = threadIdx.x;              // 0..255
    const int o = t >> 4;                   // output row
    const int i = t & 15;                   // input col
    const float* Wv = in_w + 2 * DIMC * DIMC;   // rows 32..47
    const float* bv = in_b + 2 * DIMC;

    // M[o][i] = sum_k Wout[o][k] * Wv[k][i]
    float s = 0.f;
#pragma unroll
    for (int k = 0; k < DIMC; ++k)
        s = fmaf(out_w[o * DIMC + k], Wv[k * DIMC + i], s);
    sM[o][i] = s;

    if (t < DIMC) {                          // c[t] = bout[t] + Wout[t]·bv
        float c = out_b[t];
#pragma unroll
        for (int k = 0; k < DIMC; ++k)
            c = fmaf(out_w[t * DIMC + k], bv[k], c);
        sC[t] = c;
    }
    __syncthreads();

    if (t < 64) {                            // t = q*16 + i*4 + s
        int q = t >> 4, ii = (t >> 2) & 3, ss = t & 3;
        int qq = (q + ss) & 3;
        int col = 4 * q + ii;
        g_Mq[q][ii][ss] = make_float4(sM[4 * qq + 0][col], sM[4 * qq + 1][col],
                                      sM[4 * qq + 2][col], sM[4 * qq + 3][col]);
    }
    if (t < 4)
        g_c4[t] = make_float4(sC[4 * t], sC[4 * t + 1], sC[4 * t + 2], sC[4 * t + 3]);
}

// ---- packed f32x2 helpers (f32x2 ops are PTX-only; ptxas won't auto-fuse) ----
__device__ __forceinline__ unsigned long long bcast2(float x) {
    unsigned long long r;
    asm("mov.b64 %0, {%1, %1};" : "=l"(r) : "f"(x));
    return r;
}
__device__ __forceinline__ unsigned long long ffma2(unsigned long long a,
                                                    unsigned long long b,
                                                    unsigned long long c) {
    unsigned long long d;
    asm("fma.rn.f32x2 %0, %1, %2, %3;" : "=l"(d) : "l"(a), "l"(b), "l"(c));
    return d;
}
__device__ __forceinline__ unsigned long long add2(unsigned long long a,
                                                   unsigned long long b) {
    unsigned long long d;
    asm("add.rn.f32x2 %0, %1, %2;" : "=l"(d) : "l"(a), "l"(b));
    return d;
}
__device__ __forceinline__ float2 unpack2(unsigned long long v) {
    float2 r;
    asm("mov.b64 {%0, %1}, %2;" : "=f"(r.x), "=f"(r.y) : "l"(v));
    return r;
}
__device__ __forceinline__ unsigned long long pack2(float lo, float hi) {
    unsigned long long r;
    asm("mov.b64 %0, {%1, %2};" : "=l"(r) : "f"(lo), "f"(hi));
    return r;
}
__device__ __forceinline__ unsigned long long shfl64(unsigned long long v, int src) {
    return __shfl_sync(0xffffffffu, v, src, 32);
}

#define ITERS 8   // row-groups per thread; block covers 64 rows per iter

__global__ void __launch_bounds__(256, 2)
ca_apply_kernel(const float* __restrict__ x,  // chem_16 [B,16]
                float* __restrict__ out,      // [B,16]
                unsigned int nrows)
{
    __shared__ float4 sMq[4][4][4];          // 1 KB
    __shared__ float4 sc4[4];

    const int t = threadIdx.x;
    if (t < 64) {
        int q = t >> 4, ii = (t >> 2) & 3, ss = t & 3;
        sMq[q][ii][ss] = g_Mq[q][ii][ss];
    } else if (t < 68) {
        sc4[t - 64] = g_c4[t - 64];
    }
    __syncthreads();

    const int lane = t & 31;
    const int q    = lane & 3;               // quarter owned by this lane
    const int grp  = lane & 28;
    const int src1 = grp | ((q + 1) & 3);
    const int src2 = grp | ((q + 2) & 3);
    const int src3 = grp | ((q + 3) & 3);

    // Matrix block into registers: mm[i*4+s] = two f32x2 pairs of quarter (q+s)&3
    ulonglong2 mm[16];
#pragma unroll
    for (int i = 0; i < 4; ++i)
#pragma unroll
        for (int s = 0; s < 4; ++s)
            mm[i * 4 + s] = *reinterpret_cast<const ulonglong2*>(&sMq[q][i][s]);

    unsigned long long cb0, cb1;
    { float4 c = sc4[q]; cb0 = pack2(c.x, c.y); cb1 = pack2(c.z, c.w); }

    const unsigned int row0 = blockIdx.x * (64u * ITERS) + (unsigned int)(t >> 2);
    const float4* xp = reinterpret_cast<const float4*>(x);
    float4*       op = reinterpret_cast<float4*>(out);
    const size_t  idx0 = (size_t)row0 * 4 + q;   // lane-contiguous float4 index

    // 4-deep prefetch ring for memory-level parallelism
    float4 buf[4];
#pragma unroll
    for (int k = 0; k < 4; ++k) {
        unsigned int r = row0 + 64u * k;
        buf[k] = (r < nrows) ? __ldcs(xp + idx0 + 256u * k)
                             : make_float4(0.f, 0.f, 0.f, 0.f);
    }

#pragma unroll
    for (int it = 0; it < ITERS; ++it) {
        float4 xv = buf[it & 3];
        if (it + 4 < ITERS) {
            unsigned int r = row0 + 64u * (it + 4);
            buf[it & 3] = (r < nrows) ? __ldcs(xp + idx0 + 256u * (it + 4))
                                      : make_float4(0.f, 0.f, 0.f, 0.f);
        }

        // partials: a[s*2+j] covers outputs of quarter (q+s)&3; bias seeds slot 0
        unsigned long long a[8];
        a[0] = cb0; a[1] = cb1;
        a[2] = 0ull; a[3] = 0ull; a[4] = 0ull; a[5] = 0ull; a[6] = 0ull; a[7] = 0ull;

        const float xi[4] = { xv.x, xv.y, xv.z, xv.w };
#pragma unroll
        for (int i = 0; i < 4; ++i) {
            const unsigned long long xx = bcast2(xi[i]);
#pragma unroll
            for (int s = 0; s < 4; ++s) {
                a[s * 2 + 0] = ffma2(xx, mm[i * 4 + s].x, a[s * 2 + 0]);
                a[s * 2 + 1] = ffma2(xx, mm[i * 4 + s].y, a[s * 2 + 1]);
            }
        }

        // rotated shuffle reduction: lane q gathers quarter q from all 4 lanes
        unsigned long long f0 = a[0], f1 = a[1];
        f0 = add2(f0, shfl64(a[6], src1));   // sender slot 3
        f1 = add2(f1, shfl64(a[7], src1));
        f0 = add2(f0, shfl64(a[4], src2));   // sender slot 2
        f1 = add2(f1, shfl64(a[5], src2));
        f0 = add2(f0, shfl64(a[2], src3));   // sender slot 1
        f1 = add2(f1, shfl64(a[3], src3));

        const unsigned int r = row0 + 64u * it;
        if (r < nrows) {
            float2 u = unpack2(f0), v = unpack2(f1);
            __stcs(op + idx0 + 256u * it, make_float4(u.x, u.y, v.x, v.y));
        }
    }
}

extern "C" void kernel_launch(void* const* d_in, const int* in_sizes, int n_in,
                              void* d_out, int out_size)
{
    // inputs: 0=fp_16 (unused), 1=chem_16, 2=in_proj_weight, 3=in_proj_bias,
    //         4=out_proj_weight, 5=out_proj_bias
    const float* chem  = (const float*)d_in[1];
    const float* in_w  = (const float*)d_in[2];
    const float* in_b  = (const float*)d_in[3];
    const float* out_w = (const float*)d_in[4];
    const float* out_b = (const float*)d_in[5];
    float* out = (float*)d_out;

    const unsigned int nrows = (unsigned int)(in_sizes[1] / DIMC);

    ca_setup_kernel<<<1, 256>>>(in_w, in_b, out_w, out_b);

    const unsigned int rows_per_block = 64u * ITERS;
    const unsigned int blocks = (nrows + rows_per_block - 1u) / rows_per_block;
    ca_apply_kernel<<<blocks, 256>>>(chem, out, nrows);
}